// round 10
// baseline (speedup 1.0000x reference)
#include <cuda_runtime.h>
#include <cuda_bf16.h>
#include <cstdint>

#define BATCH 16
#define NF 64
#define FIN 192
#define HW 4096
#define STEPS 16
#define EPSV 1e-5f

#define EMB_SLICE (BATCH*NF*HW)           /* 4,194,304 */
#define N_CLIP (BATCH*3*HW)               /* 196,608   */
#define OFF_EMB N_CLIP
#define OFF_RAW (OFF_EMB + 17*EMB_SLICE)

// ---- device scratch (static allocation; no cudaMalloc anywhere) ----
__device__ __align__(16) __nv_bfloat16 g_ahi[(size_t)BATCH*FIN*HW];  // normalized perception, hi
__device__ __align__(16) __nv_bfloat16 g_alo[(size_t)BATCH*FIN*HW];  // normalized perception, lo
__device__ __align__(16) __nv_bfloat16 g_whi[BATCH*NF*FIN];          // w hi  [b][o][c]
__device__ __align__(16) __nv_bfloat16 g_wlo[BATCH*NF*FIN];          // w lo
__device__ float g_bias[BATCH*NF];

// bf16 two-term split: x ~= hi + lo with |err| ~ 2^-16 |x|
__device__ __forceinline__ void bsplit(float x, __nv_bfloat16& h, __nv_bfloat16& l) {
    h = __float2bfloat16(x);
    l = __float2bfloat16(x - __bfloat162float(h));
}

// ---------------------------------------------------------------------------
// emb slice 0 = out0: zeros except channel 0, pixel (32,32)=1.  (our launch #0)
__global__ void k_init(float* __restrict__ emb0) {
    int idx = blockIdx.x * 256 + threadIdx.x;
    int within = idx & (NF*HW - 1);
    emb0[idx] = (within == (32*64 + 32)) ? 1.0f : 0.0f;
}

// blocks 0..47: w[b][o*192+c] = lat[b]·Wk[:,j] + bk[j] (bf16 hi/lo, Wk read once)
// block  48   : bias[b][o]    = lat[b]·Wb[:,o] + bb[o]          (our launch #1)
__global__ void __launch_bounds__(256) k_weights(const float* __restrict__ lat,
                                                 const float* __restrict__ Wk,
                                                 const float* __restrict__ bk,
                                                 const float* __restrict__ Wb,
                                                 const float* __restrict__ bb) {
    __shared__ float ls[BATCH][512];                  // 32 KB
    int tid = threadIdx.x;
    for (int i = tid; i < BATCH*512; i += 256) ls[i >> 9][i & 511] = lat[i];
    __syncthreads();
    if (blockIdx.x < 48) {
        int j = blockIdx.x * 256 + tid;               // 0..12287
        float bkj = bk[j];
        float acc[BATCH];
#pragma unroll
        for (int b = 0; b < BATCH; b++) acc[b] = bkj;
#pragma unroll 4
        for (int k = 0; k < 512; k++) {
            float wv = Wk[(size_t)k*12288 + j];
#pragma unroll
            for (int b = 0; b < BATCH; b++) acc[b] += ls[b][k] * wv;
        }
#pragma unroll
        for (int b = 0; b < BATCH; b++) {
            __nv_bfloat16 h, l;
            bsplit(acc[b], h, l);
            g_whi[(size_t)b*12288 + j] = h;
            g_wlo[(size_t)b*12288 + j] = l;
        }
    } else {
#pragma unroll
        for (int r = 0; r < 4; r++) {
            int idx = r*256 + tid;                    // 0..1023
            int b = idx >> 6, o = idx & 63;
            float acc = bb[o];
#pragma unroll 8
            for (int k = 0; k < 512; k++) acc += ls[b][k] * Wb[k*64 + o];
            g_bias[idx] = acc;
        }
    }
}

// ---------------------------------------------------------------------------
// 3-value block reduction over 512 threads; broadcasts result to all threads.
__device__ __forceinline__ void reduce3w(float& a, float& b, float& c,
                                         float (*red)[16], int tid) {
#pragma unroll
    for (int off = 16; off; off >>= 1) {
        a += __shfl_down_sync(0xffffffffu, a, off);
        b += __shfl_down_sync(0xffffffffu, b, off);
        c += __shfl_down_sync(0xffffffffu, c, off);
    }
    __syncthreads();
    int w = tid >> 5, l = tid & 31;
    if (l == 0) { red[0][w] = a; red[1][w] = b; red[2][w] = c; }
    __syncthreads();
    a = b = c = 0.f;
#pragma unroll
    for (int i = 0; i < 16; i++) { a += red[0][i]; b += red[1][i]; c += red[2][i]; }
}

// Per (b, source-channel): Sobel via 66x66 padded smem (branch-free), instance-norm
// stats, direct emission of normalized perception as bf16 hi/lo.  (our launch #2)
__global__ void __launch_bounds__(512) k_stats(const float* __restrict__ embt) {
    __shared__ float img[66*66];
    __shared__ float red[3][16];
    int b = blockIdx.y, c = blockIdx.x, tid = threadIdx.x;
    const float* src = embt + ((size_t)(b*NF + c)) * HW;
    for (int i = tid; i < 66*66; i += 512) img[i] = 0.f;
    __syncthreads();
    for (int i = tid; i < HW; i += 512) {
        int y = i >> 6, x = i & 63;
        img[(y + 1)*66 + (x + 1)] = src[i];
    }
    __syncthreads();

    float vv[8], sxv[8], syv[8];
    float s0 = 0.f, s1 = 0.f, s2 = 0.f;
#pragma unroll
    for (int k = 0; k < 8; k++) {
        int px = k*512 + tid;
        int p = ((px >> 6) + 1)*66 + (px & 63) + 1;
        float na = img[p-67], nb = img[p-66], nc = img[p-65];
        float nd = img[p-1],  v  = img[p],    ne = img[p+1];
        float nf = img[p+65], ng = img[p+66], nh = img[p+67];
        float sx = (nc - na + 2.f*(ne - nd) + nh - nf) * 0.125f;
        float sy = (nf - na + 2.f*(ng - nb) + nh - nc) * 0.125f;
        vv[k] = v; sxv[k] = sx; syv[k] = sy;
        s0 += v; s1 += sx; s2 += sy;
    }
    reduce3w(s0, s1, s2, red, tid);
    const float inv = 1.0f / HW;
    float mu0 = s0*inv, mu1 = s1*inv, mu2 = s2*inv;

    float q0 = 0.f, q1 = 0.f, q2 = 0.f;
#pragma unroll
    for (int k = 0; k < 8; k++) {
        float d0 = vv[k]  - mu0;  q0 += d0*d0;
        float d1 = sxv[k] - mu1;  q1 += d1*d1;
        float d2 = syv[k] - mu2;  q2 += d2*d2;
    }
    reduce3w(q0, q1, q2, red, tid);
    float rs0 = rsqrtf(q0*inv + EPSV);
    float rs1 = rsqrtf(q1*inv + EPSV);
    float rs2 = rsqrtf(q2*inv + EPSV);

    size_t c0 = ((size_t)(b*FIN + c)) * HW;
    size_t c1 = c0 + (size_t)64*HW;
    size_t c2 = c0 + (size_t)128*HW;
#pragma unroll
    for (int k = 0; k < 8; k++) {
        int px = k*512 + tid;
        __nv_bfloat16 h, l;
        bsplit((vv[k]  - mu0)*rs0, h, l); g_ahi[c0+px] = h; g_alo[c0+px] = l;
        bsplit((sxv[k] - mu1)*rs1, h, l); g_ahi[c1+px] = h; g_alo[c1+px] = l;
        bsplit((syv[k] - mu2)*rs2, h, l); g_ahi[c2+px] = h; g_alo[c2+px] = l;
    }
}

// ---------------------------------------------------------------------------
// Tensor-core GEMM, CTA = 128 px x 64 o x K=192 (12 k16 chunks), 8 warps,
// one m16 tile per warp, __launch_bounds__(256,2) -> 2 CTAs/SM (16 warps/SM).
// Profile R9 showed occ 12.2% / issue 10.5% (reg-limited 1 CTA/SM) as the wall.

__device__ __forceinline__ void ldsm4(unsigned r[4], uint32_t addr) {
    asm volatile("ldmatrix.sync.aligned.m8n8.x4.shared.b16 {%0,%1,%2,%3}, [%4];\n"
        : "=r"(r[0]), "=r"(r[1]), "=r"(r[2]), "=r"(r[3]) : "r"(addr));
}
__device__ __forceinline__ void ldsm4t(unsigned r[4], uint32_t addr) {
    asm volatile("ldmatrix.sync.aligned.m8n8.x4.trans.shared.b16 {%0,%1,%2,%3}, [%4];\n"
        : "=r"(r[0]), "=r"(r[1]), "=r"(r[2]), "=r"(r[3]) : "r"(addr));
}
__device__ __forceinline__ void mma16816(float c[4], const unsigned a[4],
                                         unsigned b0, unsigned b1) {
    asm volatile("mma.sync.aligned.m16n8k16.row.col.f32.bf16.bf16.f32 "
        "{%0,%1,%2,%3}, {%4,%5,%6,%7}, {%8,%9}, {%0,%1,%2,%3};\n"
        : "+f"(c[0]), "+f"(c[1]), "+f"(c[2]), "+f"(c[3])
        : "r"(a[0]), "r"(a[1]), "r"(a[2]), "r"(a[3]), "r"(b0), "r"(b1));
}

#define MPX 128                    /* CTA pixel tile */
#define SA_ROW 136                 /* 128 px + 8 pad (bf16) per k-row */
#define SW_ROW 24                  /* 16 k + 8 pad (bf16) per o-row   */
#define SA_BUF (16*SA_ROW)         /* 2176 elems */
#define SW_BUF (64*SW_ROW)         /* 1536 elems */
#define SA_TOT (2*2*SA_BUF)        /* 8704 */
#define SW_TOT (2*2*SW_BUF)        /* 6144 */

__global__ void __launch_bounds__(256, 2) k_gemm(const float* __restrict__ embt,
                                                 float* __restrict__ embt1,
                                                 const float* __restrict__ leak_ptr) {
    __shared__ __nv_bfloat16 sm[SA_TOT + SW_TOT];     // 29,696 B (x2 CTAs = 59.4 KB/SM)
    int b = blockIdx.y;
    int px0 = blockIdx.x * MPX;
    int tid = threadIdx.x;
    int w = tid >> 5, l = tid & 31;

    float acc[8][4];
#pragma unroll
    for (int i = 0; i < 8; i++)
#pragma unroll
        for (int j = 0; j < 4; j++) acc[i][j] = 0.f;

    // A staging: 16 rows x 16 8-px segs = 256 segs per plane; 1 per thread per plane
    int ar = tid >> 4, ax = (tid & 15)*8;
    const __nv_bfloat16* gAh = g_ahi + ((size_t)(b*FIN + ar))*HW + px0 + ax;
    const __nv_bfloat16* gAl = g_alo + ((size_t)(b*FIN + ar))*HW + px0 + ax;
    // W staging: 64 o x 2 k-halves x 2 planes = 256 segs; 1 per thread
    int wprec = tid >> 7;
    int wo = (tid & 127) >> 1, wk8 = (tid & 1) * 8;
    const __nv_bfloat16* gWp = ((wprec == 0) ? g_whi : g_wlo)
                               + (size_t)(b*NF + wo)*FIN + wk8;

    // ldmatrix lane addressing
    uint32_t smb = (uint32_t)__cvta_generic_to_shared(sm);
    int arow = ((l >> 4) & 1)*8 + (l & 7);            // k-row
    int apxl = ((l >> 3) & 1)*8;                      // px sub-offset
    int wrow = ((l >> 4) & 1)*8 + (l & 7);
    int wk   = ((l >> 3) & 1)*8;

    uint4 rah, ral, rw;
    rah = *(const uint4*)gAh;
    ral = *(const uint4*)gAl;
    rw  = *(const uint4*)gWp;

    for (int ch = 0; ch < 12; ch++) {
        int buf = ch & 1;
        {
            __nv_bfloat16* sa = sm + buf*2*SA_BUF;
            *(uint4*)(sa + ar*SA_ROW + ax)          = rah;
            *(uint4*)(sa + SA_BUF + ar*SA_ROW + ax) = ral;
            __nv_bfloat16* sw = sm + SA_TOT + buf*2*SW_BUF + wprec*SW_BUF;
            *(uint4*)(sw + wo*SW_ROW + wk8)         = rw;
        }
        __syncthreads();
        if (ch < 11) {
            gAh += (size_t)16*HW; gAl += (size_t)16*HW; gWp += 16;
            rah = *(const uint4*)gAh;
            ral = *(const uint4*)gAl;
            rw  = *(const uint4*)gWp;
        }
        unsigned a_hi[4], a_lo[4];
        uint32_t aBase = smb + (uint32_t)((buf*2*SA_BUF) + arow*SA_ROW + w*16 + apxl)*2;
        ldsm4t(a_hi, aBase);
        ldsm4t(a_lo, aBase + (uint32_t)SA_BUF*2);
#pragma unroll
        for (int i = 0; i < 4; i++) {
            unsigned wh[4], wl[4];
            uint32_t wBase = smb + (uint32_t)(SA_TOT + buf*2*SW_BUF
                              + (i*16 + wrow)*SW_ROW + wk)*2;
            ldsm4(wh, wBase);
            ldsm4(wl, wBase + (uint32_t)SW_BUF*2);
            mma16816(acc[2*i],   a_hi, wh[0], wh[1]);
            mma16816(acc[2*i],   a_hi, wl[0], wl[1]);
            mma16816(acc[2*i],   a_lo, wh[0], wh[1]);
            mma16816(acc[2*i+1], a_hi, wh[2], wh[3]);
            mma16816(acc[2*i+1], a_hi, wl[2], wl[3]);
            mma16816(acc[2*i+1], a_lo, wh[2], wh[3]);
        }
        // no trailing sync: next store targets buf^1, whose last readers were
        // chunk ch-1 (separated by this chunk's barrier).
    }

    float leak = *leak_ptr;
    leak = fminf(fmaxf(leak, 0.001f), 1000.0f);
    int mr = px0 + w*16 + (l >> 2);
#pragma unroll
    for (int nt = 0; nt < 8; nt++) {
        int o = nt*8 + (l & 3)*2;
        const float* po0 = embt  + (size_t)(b*NF + o)*HW;
        float*       pn0 = embt1 + (size_t)(b*NF + o)*HW;
        float bv0 = g_bias[b*NF + o];
        float bv1 = g_bias[b*NF + o + 1];
        pn0[mr]          = po0[mr]          + leak*(acc[nt][0] + bv0);
        pn0[mr + HW]     = po0[mr + HW]     + leak*(acc[nt][1] + bv1);
        pn0[mr + 8]      = po0[mr + 8]      + leak*(acc[nt][2] + bv0);
        pn0[mr + 8 + HW] = po0[mr + 8 + HW] + leak*(acc[nt][3] + bv1);
    }
}

// clipped RGB + raw RGB from the final state
__global__ void k_final(const float* __restrict__ emb_final, float* __restrict__ out) {
    int idx = blockIdx.x * 256 + threadIdx.x;     // < 196608
    int b = idx / (3*HW);
    int rem = idx - b*3*HW;
    int c = rem >> 12;
    int px = rem & 4095;
    float v = emb_final[((size_t)(b*NF + c))*HW + px];
    out[(size_t)OFF_RAW + idx] = v;
    out[idx] = fminf(fmaxf(v, -1.0f), 1.0f);
}

// ---------------------------------------------------------------------------
extern "C" void kernel_launch(void* const* d_in, const int* in_sizes, int n_in,
                              void* d_out, int out_size) {
    const float* lat  = (const float*)d_in[0];
    const float* Wk   = (const float*)d_in[1];
    const float* bk   = (const float*)d_in[2];
    const float* Wb   = (const float*)d_in[3];
    const float* bb   = (const float*)d_in[4];
    const float* leak = (const float*)d_in[5];
    float* out = (float*)d_out;

    // ordering: harness issues 2 hidden launches first; ncu -s 5 -c 1 thus
    // profiles OUR launch #3 = the first k_gemm.
    k_init<<<EMB_SLICE/256, 256>>>(out + OFF_EMB);             // #0
    k_weights<<<49, 256>>>(lat, Wk, bk, Wb, bb);               // #1

    for (int t = 0; t < STEPS; t++) {
        const float* et  = out + (size_t)OFF_EMB + (size_t)t * EMB_SLICE;
        float*       et1 = out + (size_t)OFF_EMB + (size_t)(t + 1) * EMB_SLICE;
        k_stats<<<dim3(64, 16), 512>>>(et);                    // #2, #4, ...
        k_gemm<<<dim3(32, 16), 256>>>(et, et1, leak);          // #3  <- ncu target
    }
    k_final<<<N_CLIP/256, 256>>>(out + OFF_EMB + (size_t)16*EMB_SLICE, out);
}

// round 12
// speedup vs baseline: 1.2022x; 1.2022x over previous
#include <cuda_runtime.h>
#include <cuda_fp16.h>
#include <cstdint>

#define BATCH 16
#define NF 64
#define FIN 192
#define HW 4096
#define STEPS 16
#define EPSV 1e-5f

#define EMB_SLICE (BATCH*NF*HW)           /* 4,194,304 */
#define N_CLIP (BATCH*3*HW)               /* 196,608   */
#define OFF_EMB N_CLIP
#define OFF_RAW (OFF_EMB + 17*EMB_SLICE)

// ---- device scratch (static allocation; no cudaMalloc anywhere) ----
__device__ __align__(16) __half g_a[(size_t)BATCH*FIN*HW];   // normalized perception, fp16
__device__ __align__(16) __half g_whi[BATCH*NF*FIN];         // w hi  [b][o][c]  fp16
__device__ __align__(16) __half g_wlo[BATCH*NF*FIN];         // w lo  (residual) fp16
__device__ float g_bias[BATCH*NF];

// fp16 two-term split of W: w ~= hi + lo captures w to ~2^-22
__device__ __forceinline__ void hsplit(float x, __half& h, __half& l) {
    h = __float2half_rn(x);
    l = __float2half_rn(x - __half2float(h));
}

// ---------------------------------------------------------------------------
// emb slice 0 = out0: zeros except channel 0, pixel (32,32)=1.  (our launch #0)
__global__ void k_init(float* __restrict__ emb0) {
    int idx = blockIdx.x * 256 + threadIdx.x;
    int within = idx & (NF*HW - 1);
    emb0[idx] = (within == (32*64 + 32)) ? 1.0f : 0.0f;
}

// blocks 0..47: w[b][o*192+c] = lat[b]·Wk[:,j] + bk[j] (fp16 hi/lo, Wk read once)
// block  48   : bias[b][o]    = lat[b]·Wb[:,o] + bb[o]          (our launch #1)
__global__ void __launch_bounds__(256) k_weights(const float* __restrict__ lat,
                                                 const float* __restrict__ Wk,
                                                 const float* __restrict__ bk,
                                                 const float* __restrict__ Wb,
                                                 const float* __restrict__ bb) {
    __shared__ float ls[BATCH][512];                  // 32 KB
    int tid = threadIdx.x;
    for (int i = tid; i < BATCH*512; i += 256) ls[i >> 9][i & 511] = lat[i];
    __syncthreads();
    if (blockIdx.x < 48) {
        int j = blockIdx.x * 256 + tid;               // 0..12287
        float bkj = bk[j];
        float acc[BATCH];
#pragma unroll
        for (int b = 0; b < BATCH; b++) acc[b] = bkj;
#pragma unroll 4
        for (int k = 0; k < 512; k++) {
            float wv = Wk[(size_t)k*12288 + j];
#pragma unroll
            for (int b = 0; b < BATCH; b++) acc[b] += ls[b][k] * wv;
        }
#pragma unroll
        for (int b = 0; b < BATCH; b++) {
            __half h, l;
            hsplit(acc[b], h, l);
            g_whi[(size_t)b*12288 + j] = h;
            g_wlo[(size_t)b*12288 + j] = l;
        }
    } else {
#pragma unroll
        for (int r = 0; r < 4; r++) {
            int idx = r*256 + tid;                    // 0..1023
            int b = idx >> 6, o = idx & 63;
            float acc = bb[o];
#pragma unroll 8
            for (int k = 0; k < 512; k++) acc += ls[b][k] * Wb[k*64 + o];
            g_bias[idx] = acc;
        }
    }
}

// ---------------------------------------------------------------------------
// 3-value block reduction over 512 threads; broadcasts result to all threads.
__device__ __forceinline__ void reduce3w(float& a, float& b, float& c,
                                         float (*red)[16], int tid) {
#pragma unroll
    for (int off = 16; off; off >>= 1) {
        a += __shfl_down_sync(0xffffffffu, a, off);
        b += __shfl_down_sync(0xffffffffu, b, off);
        c += __shfl_down_sync(0xffffffffu, c, off);
    }
    __syncthreads();
    int w = tid >> 5, l = tid & 31;
    if (l == 0) { red[0][w] = a; red[1][w] = b; red[2][w] = c; }
    __syncthreads();
    a = b = c = 0.f;
#pragma unroll
    for (int i = 0; i < 16; i++) { a += red[0][i]; b += red[1][i]; c += red[2][i]; }
}

// Per (b, source-channel): Sobel via 66x66 padded smem (branch-free), instance-norm
// stats, direct emission of normalized perception as ONE fp16 plane. (launch #2)
__global__ void __launch_bounds__(512) k_stats(const float* __restrict__ embt) {
    __shared__ float img[66*66];
    __shared__ float red[3][16];
    int b = blockIdx.y, c = blockIdx.x, tid = threadIdx.x;
    const float* src = embt + ((size_t)(b*NF + c)) * HW;
    for (int i = tid; i < 66*66; i += 512) img[i] = 0.f;
    __syncthreads();
    for (int i = tid; i < HW; i += 512) {
        int y = i >> 6, x = i & 63;
        img[(y + 1)*66 + (x + 1)] = src[i];
    }
    __syncthreads();

    float vv[8], sxv[8], syv[8];
    float s0 = 0.f, s1 = 0.f, s2 = 0.f;
#pragma unroll
    for (int k = 0; k < 8; k++) {
        int px = k*512 + tid;
        int p = ((px >> 6) + 1)*66 + (px & 63) + 1;
        float na = img[p-67], nb = img[p-66], nc = img[p-65];
        float nd = img[p-1],  v  = img[p],    ne = img[p+1];
        float nf = img[p+65], ng = img[p+66], nh = img[p+67];
        float sx = (nc - na + 2.f*(ne - nd) + nh - nf) * 0.125f;
        float sy = (nf - na + 2.f*(ng - nb) + nh - nc) * 0.125f;
        vv[k] = v; sxv[k] = sx; syv[k] = sy;
        s0 += v; s1 += sx; s2 += sy;
    }
    reduce3w(s0, s1, s2, red, tid);
    const float inv = 1.0f / HW;
    float mu0 = s0*inv, mu1 = s1*inv, mu2 = s2*inv;

    float q0 = 0.f, q1 = 0.f, q2 = 0.f;
#pragma unroll
    for (int k = 0; k < 8; k++) {
        float d0 = vv[k]  - mu0;  q0 += d0*d0;
        float d1 = sxv[k] - mu1;  q1 += d1*d1;
        float d2 = syv[k] - mu2;  q2 += d2*d2;
    }
    reduce3w(q0, q1, q2, red, tid);
    float rs0 = rsqrtf(q0*inv + EPSV);
    float rs1 = rsqrtf(q1*inv + EPSV);
    float rs2 = rsqrtf(q2*inv + EPSV);

    size_t c0 = ((size_t)(b*FIN + c)) * HW;
    size_t c1 = c0 + (size_t)64*HW;
    size_t c2 = c0 + (size_t)128*HW;
#pragma unroll
    for (int k = 0; k < 8; k++) {
        int px = k*512 + tid;
        g_a[c0+px] = __float2half_rn((vv[k]  - mu0)*rs0);
        g_a[c1+px] = __float2half_rn((sxv[k] - mu1)*rs1);
        g_a[c2+px] = __float2half_rn((syv[k] - mu2)*rs2);
    }
}

// ---------------------------------------------------------------------------
// Tensor-core GEMM, CTA = 128 px x 64 o x K=192 (12 k16 chunks), 8 warps.
// fp16: A 1-term, W 2-term -> 2 mma passes (was 3 bf16 passes).
// R10 evidence: two configs both plateau ~390 TF/s (HMMA ceiling) -> cut mma count.

__device__ __forceinline__ void ldsm4(unsigned r[4], uint32_t addr) {
    asm volatile("ldmatrix.sync.aligned.m8n8.x4.shared.b16 {%0,%1,%2,%3}, [%4];\n"
        : "=r"(r[0]), "=r"(r[1]), "=r"(r[2]), "=r"(r[3]) : "r"(addr));
}
__device__ __forceinline__ void ldsm4t(unsigned r[4], uint32_t addr) {
    asm volatile("ldmatrix.sync.aligned.m8n8.x4.trans.shared.b16 {%0,%1,%2,%3}, [%4];\n"
        : "=r"(r[0]), "=r"(r[1]), "=r"(r[2]), "=r"(r[3]) : "r"(addr));
}
__device__ __forceinline__ void mma16816(float c[4], const unsigned a[4],
                                         unsigned b0, unsigned b1) {
    asm volatile("mma.sync.aligned.m16n8k16.row.col.f32.f16.f16.f32 "
        "{%0,%1,%2,%3}, {%4,%5,%6,%7}, {%8,%9}, {%0,%1,%2,%3};\n"
        : "+f"(c[0]), "+f"(c[1]), "+f"(c[2]), "+f"(c[3])
        : "r"(a[0]), "r"(a[1]), "r"(a[2]), "r"(a[3]), "r"(b0), "r"(b1));
}

#define MPX 128                    /* CTA pixel tile */
#define SA_ROW 136                 /* 128 px + 8 pad per k-row */
#define SW_ROW 24                  /* 16 k + 8 pad per o-row   */
#define SA_BUF (16*SA_ROW)         /* 2176 elems (one plane)   */
#define SW_BUF (64*SW_ROW)         /* 1536 elems (one plane)   */
#define SA_TOT (2*SA_BUF)          /* 4352: 2 bufs x 1 plane   */
#define SW_TOT (2*2*SW_BUF)        /* 6144: 2 bufs x 2 planes  */

__global__ void __launch_bounds__(256, 2) k_gemm(const float* __restrict__ embt,
                                                 float* __restrict__ embt1,
                                                 const float* __restrict__ leak_ptr) {
    __shared__ __half sm[SA_TOT + SW_TOT];            // 20,992 B (x2 CTAs/SM)
    int b = blockIdx.y;
    int px0 = blockIdx.x * MPX;
    int tid = threadIdx.x;
    int w = tid >> 5, l = tid & 31;

    float acc[8][4];
#pragma unroll
    for (int i = 0; i < 8; i++)
#pragma unroll
        for (int j = 0; j < 4; j++) acc[i][j] = 0.f;

    // A staging: 16 rows x 16 8-px segs = 256 segs; 1 per thread
    int ar = tid >> 4, ax = (tid & 15)*8;
    const __half* gA = g_a + ((size_t)(b*FIN + ar))*HW + px0 + ax;
    // W staging: 64 o x 2 k-halves x 2 planes = 256 segs; 1 per thread
    int wprec = tid >> 7;
    int wo = (tid & 127) >> 1, wk8 = (tid & 1) * 8;
    const __half* gWp = ((wprec == 0) ? g_whi : g_wlo)
                        + (size_t)(b*NF + wo)*FIN + wk8;

    // ldmatrix lane addressing
    uint32_t smb = (uint32_t)__cvta_generic_to_shared(sm);
    int arow = ((l >> 4) & 1)*8 + (l & 7);            // k-row
    int apxl = ((l >> 3) & 1)*8;                      // px sub-offset
    int wrow = ((l >> 4) & 1)*8 + (l & 7);
    int wk   = ((l >> 3) & 1)*8;

    uint4 rah, rw;
    rah = *(const uint4*)gA;
    rw  = *(const uint4*)gWp;

    for (int ch = 0; ch < 12; ch++) {
        int buf = ch & 1;
        {
            __half* sa = sm + buf*SA_BUF;
            *(uint4*)(sa + ar*SA_ROW + ax) = rah;
            __half* sw = sm + SA_TOT + buf*2*SW_BUF + wprec*SW_BUF;
            *(uint4*)(sw + wo*SW_ROW + wk8) = rw;
        }
        __syncthreads();
        if (ch < 11) {
            gA += (size_t)16*HW; gWp += 16;
            rah = *(const uint4*)gA;
            rw  = *(const uint4*)gWp;
        }
        unsigned a[4];
        uint32_t aBase = smb + (uint32_t)(buf*SA_BUF + arow*SA_ROW + w*16 + apxl)*2;
        ldsm4t(a, aBase);
#pragma unroll
        for (int i = 0; i < 4; i++) {
            unsigned wh[4], wl[4];
            uint32_t wBase = smb + (uint32_t)(SA_TOT + buf*2*SW_BUF
                              + (i*16 + wrow)*SW_ROW + wk)*2;
            ldsm4(wh, wBase);
            ldsm4(wl, wBase + (uint32_t)SW_BUF*2);
            mma16816(acc[2*i],   a, wh[0], wh[1]);
            mma16816(acc[2*i],   a, wl[0], wl[1]);
            mma16816(acc[2*i+1], a, wh[2], wh[3]);
            mma16816(acc[2*i+1], a, wl[2], wl[3]);
        }
        // no trailing sync: next store targets buf^1, whose last readers were
        // chunk ch-1 (separated by this chunk's barrier).
    }

    float leak = *leak_ptr;
    leak = fminf(fmaxf(leak, 0.001f), 1000.0f);
    int mr = px0 + w*16 + (l >> 2);
#pragma unroll
    for (int nt = 0; nt < 8; nt++) {
        int o = nt*8 + (l & 3)*2;
        const float* po0 = embt  + (size_t)(b*NF + o)*HW;
        float*       pn0 = embt1 + (size_t)(b*NF + o)*HW;
        float bv0 = g_bias[b*NF + o];
        float bv1 = g_bias[b*NF + o + 1];
        pn0[mr]          = po0[mr]          + leak*(acc[nt][0] + bv0);
        pn0[mr + HW]     = po0[mr + HW]     + leak*(acc[nt][1] + bv1);
        pn0[mr + 8]      = po0[mr + 8]      + leak*(acc[nt][2] + bv0);
        pn0[mr + 8 + HW] = po0[mr + 8 + HW] + leak*(acc[nt][3] + bv1);
    }
}

// clipped RGB + raw RGB from the final state
__global__ void k_final(const float* __restrict__ emb_final, float* __restrict__ out) {
    int idx = blockIdx.x * 256 + threadIdx.x;     // < 196608
    int b = idx / (3*HW);
    int rem = idx - b*3*HW;
    int c = rem >> 12;
    int px = rem & 4095;
    float v = emb_final[((size_t)(b*NF + c))*HW + px];
    out[(size_t)OFF_RAW + idx] = v;
    out[idx] = fminf(fmaxf(v, -1.0f), 1.0f);
}

// ---------------------------------------------------------------------------
extern "C" void kernel_launch(void* const* d_in, const int* in_sizes, int n_in,
                              void* d_out, int out_size) {
    const float* lat  = (const float*)d_in[0];
    const float* Wk   = (const float*)d_in[1];
    const float* bk   = (const float*)d_in[2];
    const float* Wb   = (const float*)d_in[3];
    const float* bb   = (const float*)d_in[4];
    const float* leak = (const float*)d_in[5];
    float* out = (float*)d_out;

    // ordering: harness issues 2 hidden launches first; ncu -s 5 -c 1 thus
    // profiles OUR launch #3 = the first k_gemm.
    k_init<<<EMB_SLICE/256, 256>>>(out + OFF_EMB);             // #0
    k_weights<<<49, 256>>>(lat, Wk, bk, Wb, bb);               // #1

    for (int t = 0; t < STEPS; t++) {
        const float* et  = out + (size_t)OFF_EMB + (size_t)t * EMB_SLICE;
        float*       et1 = out + (size_t)OFF_EMB + (size_t)(t + 1) * EMB_SLICE;
        k_stats<<<dim3(64, 16), 512>>>(et);                    // #2, #4, ...
        k_gemm<<<dim3(32, 16), 256>>>(et, et1, leak);          // #3  <- ncu target
    }
    k_final<<<N_CLIP/256, 256>>>(out + OFF_EMB + (size_t)16*EMB_SLICE, out);
}

// round 13
// speedup vs baseline: 1.2827x; 1.0670x over previous
#include <cuda_runtime.h>
#include <cuda_fp16.h>
#include <cstdint>

#define BATCH 16
#define NF 64
#define FIN 192
#define HW 4096
#define STEPS 16
#define EPSV 1e-5f

#define EMB_SLICE (BATCH*NF*HW)           /* 4,194,304 */
#define N_CLIP (BATCH*3*HW)               /* 196,608   */
#define OFF_EMB N_CLIP
#define OFF_RAW (OFF_EMB + 17*EMB_SLICE)

// ---- device scratch (static allocation; no cudaMalloc anywhere) ----
__device__ __align__(16) __half g_a[(size_t)BATCH*FIN*HW];   // normalized perception, fp16
__device__ __align__(16) __half g_whi[BATCH*NF*FIN];         // w hi  [b][o][c]  fp16
__device__ __align__(16) __half g_wlo[BATCH*NF*FIN];         // w lo  (residual) fp16
__device__ float g_bias[BATCH*NF];

// fp16 two-term split of W: w ~= hi + lo captures w to ~2^-22
__device__ __forceinline__ void hsplit(float x, __half& h, __half& l) {
    h = __float2half_rn(x);
    l = __float2half_rn(x - __half2float(h));
}

// ---------------------------------------------------------------------------
// emb slice 0 = out0: zeros except channel 0, pixel (32,32)=1.  (our launch #0)
__global__ void k_init(float* __restrict__ emb0) {
    int idx = blockIdx.x * 256 + threadIdx.x;
    int within = idx & (NF*HW - 1);
    emb0[idx] = (within == (32*64 + 32)) ? 1.0f : 0.0f;
}

// blocks 0..47: w[b][o*192+c] = lat[b]·Wk[:,j] + bk[j] (fp16 hi/lo, Wk read once)
// block  48   : bias[b][o]    = lat[b]·Wb[:,o] + bb[o]          (our launch #1)
__global__ void __launch_bounds__(256) k_weights(const float* __restrict__ lat,
                                                 const float* __restrict__ Wk,
                                                 const float* __restrict__ bk,
                                                 const float* __restrict__ Wb,
                                                 const float* __restrict__ bb) {
    __shared__ float ls[BATCH][512];                  // 32 KB
    int tid = threadIdx.x;
    for (int i = tid; i < BATCH*512; i += 256) ls[i >> 9][i & 511] = lat[i];
    __syncthreads();
    if (blockIdx.x < 48) {
        int j = blockIdx.x * 256 + tid;               // 0..12287
        float bkj = bk[j];
        float acc[BATCH];
#pragma unroll
        for (int b = 0; b < BATCH; b++) acc[b] = bkj;
#pragma unroll 4
        for (int k = 0; k < 512; k++) {
            float wv = Wk[(size_t)k*12288 + j];
#pragma unroll
            for (int b = 0; b < BATCH; b++) acc[b] += ls[b][k] * wv;
        }
#pragma unroll
        for (int b = 0; b < BATCH; b++) {
            __half h, l;
            hsplit(acc[b], h, l);
            g_whi[(size_t)b*12288 + j] = h;
            g_wlo[(size_t)b*12288 + j] = l;
        }
    } else {
#pragma unroll
        for (int r = 0; r < 4; r++) {
            int idx = r*256 + tid;                    // 0..1023
            int b = idx >> 6, o = idx & 63;
            float acc = bb[o];
#pragma unroll 8
            for (int k = 0; k < 512; k++) acc += ls[b][k] * Wb[k*64 + o];
            g_bias[idx] = acc;
        }
    }
}

// ---------------------------------------------------------------------------
// 3-value block reduction over 512 threads; broadcasts result to all threads.
__device__ __forceinline__ void reduce3w(float& a, float& b, float& c,
                                         float (*red)[16], int tid) {
#pragma unroll
    for (int off = 16; off; off >>= 1) {
        a += __shfl_down_sync(0xffffffffu, a, off);
        b += __shfl_down_sync(0xffffffffu, b, off);
        c += __shfl_down_sync(0xffffffffu, c, off);
    }
    __syncthreads();
    int w = tid >> 5, l = tid & 31;
    if (l == 0) { red[0][w] = a; red[1][w] = b; red[2][w] = c; }
    __syncthreads();
    a = b = c = 0.f;
#pragma unroll
    for (int i = 0; i < 16; i++) { a += red[0][i]; b += red[1][i]; c += red[2][i]; }
}

// Per (b, source-channel): Sobel via 66x66 padded smem (branch-free), instance-norm
// stats, direct emission of normalized perception as ONE fp16 plane. (launch #2)
__global__ void __launch_bounds__(512) k_stats(const float* __restrict__ embt) {
    __shared__ float img[66*66];
    __shared__ float red[3][16];
    int b = blockIdx.y, c = blockIdx.x, tid = threadIdx.x;
    const float* src = embt + ((size_t)(b*NF + c)) * HW;
    for (int i = tid; i < 66*66; i += 512) img[i] = 0.f;
    __syncthreads();
    for (int i = tid; i < HW; i += 512) {
        int y = i >> 6, x = i & 63;
        img[(y + 1)*66 + (x + 1)] = src[i];
    }
    __syncthreads();

    float vv[8], sxv[8], syv[8];
    float s0 = 0.f, s1 = 0.f, s2 = 0.f;
#pragma unroll
    for (int k = 0; k < 8; k++) {
        int px = k*512 + tid;
        int p = ((px >> 6) + 1)*66 + (px & 63) + 1;
        float na = img[p-67], nb = img[p-66], nc = img[p-65];
        float nd = img[p-1],  v  = img[p],    ne = img[p+1];
        float nf = img[p+65], ng = img[p+66], nh = img[p+67];
        float sx = (nc - na + 2.f*(ne - nd) + nh - nf) * 0.125f;
        float sy = (nf - na + 2.f*(ng - nb) + nh - nc) * 0.125f;
        vv[k] = v; sxv[k] = sx; syv[k] = sy;
        s0 += v; s1 += sx; s2 += sy;
    }
    reduce3w(s0, s1, s2, red, tid);
    const float inv = 1.0f / HW;
    float mu0 = s0*inv, mu1 = s1*inv, mu2 = s2*inv;

    float q0 = 0.f, q1 = 0.f, q2 = 0.f;
#pragma unroll
    for (int k = 0; k < 8; k++) {
        float d0 = vv[k]  - mu0;  q0 += d0*d0;
        float d1 = sxv[k] - mu1;  q1 += d1*d1;
        float d2 = syv[k] - mu2;  q2 += d2*d2;
    }
    reduce3w(q0, q1, q2, red, tid);
    float rs0 = rsqrtf(q0*inv + EPSV);
    float rs1 = rsqrtf(q1*inv + EPSV);
    float rs2 = rsqrtf(q2*inv + EPSV);

    size_t c0 = ((size_t)(b*FIN + c)) * HW;
    size_t c1 = c0 + (size_t)64*HW;
    size_t c2 = c0 + (size_t)128*HW;
#pragma unroll
    for (int k = 0; k < 8; k++) {
        int px = k*512 + tid;
        g_a[c0+px] = __float2half_rn((vv[k]  - mu0)*rs0);
        g_a[c1+px] = __float2half_rn((sxv[k] - mu1)*rs1);
        g_a[c2+px] = __float2half_rn((syv[k] - mu2)*rs2);
    }
}

// ---------------------------------------------------------------------------
// Tensor-core GEMM, CTA = 128 px x 64 o, K=192 in SIX k32 chunks (was 12 k16).
// cp.async staging (no register roundtrip), 2-stage, ONE barrier per chunk.
// R12 evidence: issue 10%, nothing saturated -> latency-bound mainloop structure.

__device__ __forceinline__ void ldsm4(unsigned r[4], uint32_t addr) {
    asm volatile("ldmatrix.sync.aligned.m8n8.x4.shared.b16 {%0,%1,%2,%3}, [%4];\n"
        : "=r"(r[0]), "=r"(r[1]), "=r"(r[2]), "=r"(r[3]) : "r"(addr));
}
__device__ __forceinline__ void ldsm4t(unsigned r[4], uint32_t addr) {
    asm volatile("ldmatrix.sync.aligned.m8n8.x4.trans.shared.b16 {%0,%1,%2,%3}, [%4];\n"
        : "=r"(r[0]), "=r"(r[1]), "=r"(r[2]), "=r"(r[3]) : "r"(addr));
}
__device__ __forceinline__ void mma16816(float c[4], const unsigned a[4],
                                         unsigned b0, unsigned b1) {
    asm volatile("mma.sync.aligned.m16n8k16.row.col.f32.f16.f16.f32 "
        "{%0,%1,%2,%3}, {%4,%5,%6,%7}, {%8,%9}, {%0,%1,%2,%3};\n"
        : "+f"(c[0]), "+f"(c[1]), "+f"(c[2]), "+f"(c[3])
        : "r"(a[0]), "r"(a[1]), "r"(a[2]), "r"(a[3]), "r"(b0), "r"(b1));
}
__device__ __forceinline__ void cp16(uint32_t smem_dst, const void* gsrc) {
    asm volatile("cp.async.cg.shared.global [%0], [%1], 16;\n"
        :: "r"(smem_dst), "l"(gsrc));
}
__device__ __forceinline__ void cp_commit() {
    asm volatile("cp.async.commit_group;\n");
}
__device__ __forceinline__ void cp_wait0() {
    asm volatile("cp.async.wait_group 0;\n");
}

#define MPX 128                    /* CTA pixel tile */
#define KC 32                      /* K per chunk */
#define NCH 6                      /* 192/32 */
#define SA_ROW 136                 /* 128 px + 8 pad per k-row */
#define SW_ROW 40                  /* 32 k + 8 pad per o-row   */
#define SA_BUF (KC*SA_ROW)         /* 4352 elems */
#define SW_PLANE (64*SW_ROW)       /* 2560 elems */
#define BUF_ELEM (SA_BUF + 2*SW_PLANE)  /* 9472 */
/* total smem: 2 bufs x 9472 x 2B = 37,888 B */

__global__ void __launch_bounds__(256, 2) k_gemm(const float* __restrict__ embt,
                                                 float* __restrict__ embt1,
                                                 const float* __restrict__ leak_ptr) {
    __shared__ __half sm[2*BUF_ELEM];
    int b = blockIdx.y;
    int px0 = blockIdx.x * MPX;
    int tid = threadIdx.x;
    int w = tid >> 5, l = tid & 31;
    uint32_t smb = (uint32_t)__cvta_generic_to_shared(sm);

    float acc[8][4];
#pragma unroll
    for (int i = 0; i < 8; i++)
#pragma unroll
        for (int j = 0; j < 4; j++) acc[i][j] = 0.f;

    // A staging: 32 k-rows x 16 8-px segs = 512 segs; threads t, t+256
    int ar0 = tid >> 4,        ax0 = (tid & 15)*8;          // segs 0..255
    int ar1 = (tid + 256) >> 4, ax1 = (tid & 15)*8;         // segs 256..511
    const __half* gA0 = g_a + ((size_t)(b*FIN + ar0))*HW + px0 + ax0;
    const __half* gA1 = g_a + ((size_t)(b*FIN + ar1))*HW + px0 + ax1;
    // W staging: 2 planes x 64 o x 4 8-k segs = 512 segs; thread t -> plane0 seg t, plane1 seg t
    int wo = tid >> 2, wk8 = (tid & 3)*8;
    const __half* gWh = g_whi + (size_t)(b*NF + wo)*FIN + wk8;
    const __half* gWl = g_wlo + (size_t)(b*NF + wo)*FIN + wk8;
    // smem element offsets (within buf)
    uint32_t sA0 = (uint32_t)(ar0*SA_ROW + ax0);
    uint32_t sA1 = (uint32_t)(ar1*SA_ROW + ax1);
    uint32_t sWh = (uint32_t)(SA_BUF + wo*SW_ROW + wk8);
    uint32_t sWl = (uint32_t)(SA_BUF + SW_PLANE + wo*SW_ROW + wk8);

    // ldmatrix lane addressing
    int arow = ((l >> 4) & 1)*8 + (l & 7);            // k-row within k16 group
    int apxl = ((l >> 3) & 1)*8;                      // px sub-offset
    int wrow = ((l >> 4) & 1)*8 + (l & 7);
    int wkl  = ((l >> 3) & 1)*8;

    // issue chunk 0
    {
        uint32_t base = smb;
        cp16(base + sA0*2, gA0);
        cp16(base + sA1*2, gA1);
        cp16(base + sWh*2, gWh);
        cp16(base + sWl*2, gWl);
        cp_commit();
    }

    for (int ch = 0; ch < NCH; ch++) {
        int buf = ch & 1;
        cp_wait0();                 // chunk ch resident (ch+1 not yet issued)
        __syncthreads();
        if (ch + 1 < NCH) {         // issue chunk ch+1 into buf^1 (safe post-sync)
            uint32_t base = smb + (uint32_t)((buf ^ 1)*BUF_ELEM)*2;
            size_t go = (size_t)(ch + 1)*KC;
            cp16(base + sA0*2, gA0 + go*HW);
            cp16(base + sA1*2, gA1 + go*HW);
            cp16(base + sWh*2, gWh + go);
            cp16(base + sWl*2, gWl + go);
            cp_commit();
        }
        uint32_t bb0 = smb + (uint32_t)(buf*BUF_ELEM)*2;
#pragma unroll
        for (int g = 0; g < 2; g++) {                 // two k16 groups per chunk
            unsigned a[4];
            ldsm4t(a, bb0 + (uint32_t)((g*16 + arow)*SA_ROW + w*16 + apxl)*2);
#pragma unroll
            for (int i = 0; i < 4; i++) {
                unsigned wh[4], wl[4];
                uint32_t wb = bb0 + (uint32_t)(SA_BUF + (i*16 + wrow)*SW_ROW + g*16 + wkl)*2;
                ldsm4(wh, wb);
                ldsm4(wl, wb + (uint32_t)SW_PLANE*2);
                mma16816(acc[2*i],   a, wh[0], wh[1]);
                mma16816(acc[2*i],   a, wl[0], wl[1]);
                mma16816(acc[2*i+1], a, wh[2], wh[3]);
                mma16816(acc[2*i+1], a, wl[2], wl[3]);
            }
        }
        // no trailing sync: buf^1 is written only after the NEXT iteration's
        // barrier, by which time all warps are done with it.
    }

    float leak = *leak_ptr;
    leak = fminf(fmaxf(leak, 0.001f), 1000.0f);
    int mr = px0 + w*16 + (l >> 2);
#pragma unroll
    for (int nt = 0; nt < 8; nt++) {
        int o = nt*8 + (l & 3)*2;
        const float* po0 = embt  + (size_t)(b*NF + o)*HW;
        float*       pn0 = embt1 + (size_t)(b*NF + o)*HW;
        float bv0 = g_bias[b*NF + o];
        float bv1 = g_bias[b*NF + o + 1];
        pn0[mr]          = po0[mr]          + leak*(acc[nt][0] + bv0);
        pn0[mr + HW]     = po0[mr + HW]     + leak*(acc[nt][1] + bv1);
        pn0[mr + 8]      = po0[mr + 8]      + leak*(acc[nt][2] + bv0);
        pn0[mr + 8 + HW] = po0[mr + 8 + HW] + leak*(acc[nt][3] + bv1);
    }
}

// clipped RGB + raw RGB from the final state
__global__ void k_final(const float* __restrict__ emb_final, float* __restrict__ out) {
    int idx = blockIdx.x * 256 + threadIdx.x;     // < 196608
    int b = idx / (3*HW);
    int rem = idx - b*3*HW;
    int c = rem >> 12;
    int px = rem & 4095;
    float v = emb_final[((size_t)(b*NF + c))*HW + px];
    out[(size_t)OFF_RAW + idx] = v;
    out[idx] = fminf(fmaxf(v, -1.0f), 1.0f);
}

// ---------------------------------------------------------------------------
extern "C" void kernel_launch(void* const* d_in, const int* in_sizes, int n_in,
                              void* d_out, int out_size) {
    const float* lat  = (const float*)d_in[0];
    const float* Wk   = (const float*)d_in[1];
    const float* bk   = (const float*)d_in[2];
    const float* Wb   = (const float*)d_in[3];
    const float* bb   = (const float*)d_in[4];
    const float* leak = (const float*)d_in[5];
    float* out = (float*)d_out;

    // ordering: harness issues 2 hidden launches first; ncu -s 5 -c 1 thus
    // profiles OUR launch #3 = the first k_gemm.
    k_init<<<EMB_SLICE/256, 256>>>(out + OFF_EMB);             // #0
    k_weights<<<49, 256>>>(lat, Wk, bk, Wb, bb);               // #1

    for (int t = 0; t < STEPS; t++) {
        const float* et  = out + (size_t)OFF_EMB + (size_t)t * EMB_SLICE;
        float*       et1 = out + (size_t)OFF_EMB + (size_t)(t + 1) * EMB_SLICE;
        k_stats<<<dim3(64, 16), 512>>>(et);                    // #2, #4, ...
        k_gemm<<<dim3(32, 16), 256>>>(et, et1, leak);          // #3  <- ncu target
    }
    k_final<<<N_CLIP/256, 256>>>(out + OFF_EMB + (size_t)16*EMB_SLICE, out);
}

// round 14
// speedup vs baseline: 1.3787x; 1.0748x over previous
#include <cuda_runtime.h>
#include <cuda_fp16.h>
#include <cstdint>

#define BATCH 16
#define NF 64
#define FIN 192
#define HW 4096
#define STEPS 16
#define EPSV 1e-5f

#define EMB_SLICE (BATCH*NF*HW)           /* 4,194,304 */
#define N_CLIP (BATCH*3*HW)               /* 196,608   */
#define OFF_EMB N_CLIP
#define OFF_RAW (OFF_EMB + 17*EMB_SLICE)

// ---- device scratch (static allocation; no cudaMalloc anywhere) ----
__device__ __align__(16) __half g_a[(size_t)BATCH*FIN*HW];   // normalized perception, fp16
__device__ __align__(16) __half g_whi[BATCH*NF*FIN];         // w hi  [b][o][c]  fp16
__device__ __align__(16) __half g_wlo[BATCH*NF*FIN];         // w lo  (residual) fp16
__device__ float g_bias[BATCH*NF];

// fp16 two-term split of W: w ~= hi + lo captures w to ~2^-22
__device__ __forceinline__ void hsplit(float x, __half& h, __half& l) {
    h = __float2half_rn(x);
    l = __float2half_rn(x - __half2float(h));
}

// ---------------------------------------------------------------------------
// emb slice 0 = out0: zeros except channel 0, pixel (32,32)=1.  (our launch #0)
__global__ void k_init(float* __restrict__ emb0) {
    int idx = blockIdx.x * 256 + threadIdx.x;
    int within = idx & (NF*HW - 1);
    emb0[idx] = (within == (32*64 + 32)) ? 1.0f : 0.0f;
}

// blocks 0..47: w[b][o*192+c] = lat[b]·Wk[:,j] + bk[j] (fp16 hi/lo, Wk read once)
// block  48   : bias[b][o]    = lat[b]·Wb[:,o] + bb[o]          (our launch #1)
__global__ void __launch_bounds__(256) k_weights(const float* __restrict__ lat,
                                                 const float* __restrict__ Wk,
                                                 const float* __restrict__ bk,
                                                 const float* __restrict__ Wb,
                                                 const float* __restrict__ bb) {
    __shared__ float ls[BATCH][512];                  // 32 KB
    int tid = threadIdx.x;
    for (int i = tid; i < BATCH*512; i += 256) ls[i >> 9][i & 511] = lat[i];
    __syncthreads();
    if (blockIdx.x < 48) {
        int j = blockIdx.x * 256 + tid;               // 0..12287
        float bkj = bk[j];
        float acc[BATCH];
#pragma unroll
        for (int b = 0; b < BATCH; b++) acc[b] = bkj;
#pragma unroll 4
        for (int k = 0; k < 512; k++) {
            float wv = Wk[(size_t)k*12288 + j];
#pragma unroll
            for (int b = 0; b < BATCH; b++) acc[b] += ls[b][k] * wv;
        }
#pragma unroll
        for (int b = 0; b < BATCH; b++) {
            __half h, l;
            hsplit(acc[b], h, l);
            g_whi[(size_t)b*12288 + j] = h;
            g_wlo[(size_t)b*12288 + j] = l;
        }
    } else {
#pragma unroll
        for (int r = 0; r < 4; r++) {
            int idx = r*256 + tid;                    // 0..1023
            int b = idx >> 6, o = idx & 63;
            float acc = bb[o];
#pragma unroll 8
            for (int k = 0; k < 512; k++) acc += ls[b][k] * Wb[k*64 + o];
            g_bias[idx] = acc;
        }
    }
}

// ---------------------------------------------------------------------------
// 6-value block reduction over 512 threads; broadcasts results to all threads.
__device__ __forceinline__ void reduce6w(float& a, float& b, float& c,
                                         float& d, float& e, float& f,
                                         float (*red)[16], int tid) {
#pragma unroll
    for (int off = 16; off; off >>= 1) {
        a += __shfl_down_sync(0xffffffffu, a, off);
        b += __shfl_down_sync(0xffffffffu, b, off);
        c += __shfl_down_sync(0xffffffffu, c, off);
        d += __shfl_down_sync(0xffffffffu, d, off);
        e += __shfl_down_sync(0xffffffffu, e, off);
        f += __shfl_down_sync(0xffffffffu, f, off);
    }
    __syncthreads();
    int w = tid >> 5, l = tid & 31;
    if (l == 0) { red[0][w]=a; red[1][w]=b; red[2][w]=c; red[3][w]=d; red[4][w]=e; red[5][w]=f; }
    __syncthreads();
    a = b = c = d = e = f = 0.f;
#pragma unroll
    for (int i = 0; i < 16; i++) {
        a += red[0][i]; b += red[1][i]; c += red[2][i];
        d += red[3][i]; e += red[4][i]; f += red[5][i];
    }
}

// Per (b, source-channel): Sobel via 66x66 padded smem, SINGLE-PASS stats
// (E[x^2]-mu^2 variance), fp16 emission of normalized perception. (launch #2)
__global__ void __launch_bounds__(512) k_stats(const float* __restrict__ embt) {
    __shared__ float img[66*66];
    __shared__ float red[6][16];
    int b = blockIdx.y, c = blockIdx.x, tid = threadIdx.x;
    const float* src = embt + ((size_t)(b*NF + c)) * HW;
    for (int i = tid; i < 66*66; i += 512) img[i] = 0.f;
    __syncthreads();
    for (int i = tid; i < HW; i += 512) {
        int y = i >> 6, x = i & 63;
        img[(y + 1)*66 + (x + 1)] = src[i];
    }
    __syncthreads();

    float vv[8], sxv[8], syv[8];
    float s0=0.f, s1=0.f, s2=0.f, q0=0.f, q1=0.f, q2=0.f;
#pragma unroll
    for (int k = 0; k < 8; k++) {
        int px = k*512 + tid;
        int p = ((px >> 6) + 1)*66 + (px & 63) + 1;
        float na = img[p-67], nb = img[p-66], nc = img[p-65];
        float nd = img[p-1],  v  = img[p],    ne = img[p+1];
        float nf = img[p+65], ng = img[p+66], nh = img[p+67];
        float sx = (nc - na + 2.f*(ne - nd) + nh - nf) * 0.125f;
        float sy = (nf - na + 2.f*(ng - nb) + nh - nc) * 0.125f;
        vv[k] = v; sxv[k] = sx; syv[k] = sy;
        s0 += v;     s1 += sx;     s2 += sy;
        q0 += v*v;   q1 += sx*sx;  q2 += sy*sy;
    }
    reduce6w(s0, s1, s2, q0, q1, q2, red, tid);
    const float inv = 1.0f / HW;
    float mu0 = s0*inv, mu1 = s1*inv, mu2 = s2*inv;
    float rs0 = rsqrtf(fmaxf(q0*inv - mu0*mu0, 0.f) + EPSV);
    float rs1 = rsqrtf(fmaxf(q1*inv - mu1*mu1, 0.f) + EPSV);
    float rs2 = rsqrtf(fmaxf(q2*inv - mu2*mu2, 0.f) + EPSV);

    size_t c0 = ((size_t)(b*FIN + c)) * HW;
    size_t c1 = c0 + (size_t)64*HW;
    size_t c2 = c0 + (size_t)128*HW;
#pragma unroll
    for (int k = 0; k < 8; k++) {
        int px = k*512 + tid;
        g_a[c0+px] = __float2half_rn((vv[k]  - mu0)*rs0);
        g_a[c1+px] = __float2half_rn((sxv[k] - mu1)*rs1);
        g_a[c2+px] = __float2half_rn((syv[k] - mu2)*rs2);
    }
}

// ---------------------------------------------------------------------------
// Tensor-core GEMM, CTA = 128 px x 64 o, K=192 in 6 k32 chunks.
// 3-STAGE cp.async pipeline (chunk ch+2 in flight during compute of ch) and
// hi/lo mma passes separated to break accumulator RAW chains.

__device__ __forceinline__ void ldsm4(unsigned r[4], uint32_t addr) {
    asm volatile("ldmatrix.sync.aligned.m8n8.x4.shared.b16 {%0,%1,%2,%3}, [%4];\n"
        : "=r"(r[0]), "=r"(r[1]), "=r"(r[2]), "=r"(r[3]) : "r"(addr));
}
__device__ __forceinline__ void ldsm4t(unsigned r[4], uint32_t addr) {
    asm volatile("ldmatrix.sync.aligned.m8n8.x4.trans.shared.b16 {%0,%1,%2,%3}, [%4];\n"
        : "=r"(r[0]), "=r"(r[1]), "=r"(r[2]), "=r"(r[3]) : "r"(addr));
}
__device__ __forceinline__ void mma16816(float c[4], const unsigned a[4],
                                         unsigned b0, unsigned b1) {
    asm volatile("mma.sync.aligned.m16n8k16.row.col.f32.f16.f16.f32 "
        "{%0,%1,%2,%3}, {%4,%5,%6,%7}, {%8,%9}, {%0,%1,%2,%3};\n"
        : "+f"(c[0]), "+f"(c[1]), "+f"(c[2]), "+f"(c[3])
        : "r"(a[0]), "r"(a[1]), "r"(a[2]), "r"(a[3]), "r"(b0), "r"(b1));
}
__device__ __forceinline__ void cp16(uint32_t smem_dst, const void* gsrc) {
    asm volatile("cp.async.cg.shared.global [%0], [%1], 16;\n"
        :: "r"(smem_dst), "l"(gsrc));
}
__device__ __forceinline__ void cp_commit() {
    asm volatile("cp.async.commit_group;\n");
}
__device__ __forceinline__ void cp_wait0() {
    asm volatile("cp.async.wait_group 0;\n");
}
__device__ __forceinline__ void cp_wait1() {
    asm volatile("cp.async.wait_group 1;\n");
}

#define MPX 128                    /* CTA pixel tile */
#define KC 32                      /* K per chunk */
#define NCH 6                      /* 192/32 */
#define NSTG 3                     /* pipeline stages */
#define SA_ROW 136                 /* 128 px + 8 pad per k-row */
#define SW_ROW 40                  /* 32 k + 8 pad per o-row   */
#define SA_BUF (KC*SA_ROW)         /* 4352 elems */
#define SW_PLANE (64*SW_ROW)       /* 2560 elems */
#define BUF_ELEM (SA_BUF + 2*SW_PLANE)  /* 9472 */
#define SMEM_BYTES (NSTG*BUF_ELEM*2)    /* 56,832 B dynamic */

__global__ void __launch_bounds__(256, 2) k_gemm(const float* __restrict__ embt,
                                                 float* __restrict__ embt1,
                                                 const float* __restrict__ leak_ptr) {
    extern __shared__ __half sm[];
    int b = blockIdx.y;
    int px0 = blockIdx.x * MPX;
    int tid = threadIdx.x;
    int w = tid >> 5, l = tid & 31;
    uint32_t smb = (uint32_t)__cvta_generic_to_shared(sm);

    float acc[8][4];
#pragma unroll
    for (int i = 0; i < 8; i++)
#pragma unroll
        for (int j = 0; j < 4; j++) acc[i][j] = 0.f;

    // A staging: 32 k-rows x 16 8-px segs = 512 segs; threads t, t+256
    int ar0 = tid >> 4,         ax0 = (tid & 15)*8;
    int ar1 = (tid + 256) >> 4, ax1 = (tid & 15)*8;
    const __half* gA0 = g_a + ((size_t)(b*FIN + ar0))*HW + px0 + ax0;
    const __half* gA1 = g_a + ((size_t)(b*FIN + ar1))*HW + px0 + ax1;
    // W staging: 2 planes x 64 o x 4 8-k segs; thread t covers both planes' seg t
    int wo = tid >> 2, wk8 = (tid & 3)*8;
    const __half* gWh = g_whi + (size_t)(b*NF + wo)*FIN + wk8;
    const __half* gWl = g_wlo + (size_t)(b*NF + wo)*FIN + wk8;
    uint32_t sA0 = (uint32_t)(ar0*SA_ROW + ax0);
    uint32_t sA1 = (uint32_t)(ar1*SA_ROW + ax1);
    uint32_t sWh = (uint32_t)(SA_BUF + wo*SW_ROW + wk8);
    uint32_t sWl = (uint32_t)(SA_BUF + SW_PLANE + wo*SW_ROW + wk8);

    // ldmatrix lane addressing
    int arow = ((l >> 4) & 1)*8 + (l & 7);
    int apxl = ((l >> 3) & 1)*8;
    int wrow = ((l >> 4) & 1)*8 + (l & 7);
    int wkl  = ((l >> 3) & 1)*8;

    // prologue: issue chunks 0 and 1
#pragma unroll
    for (int pc = 0; pc < 2; pc++) {
        uint32_t base = smb + (uint32_t)(pc*BUF_ELEM)*2;
        size_t go = (size_t)pc*KC;
        cp16(base + sA0*2, gA0 + go*HW);
        cp16(base + sA1*2, gA1 + go*HW);
        cp16(base + sWh*2, gWh + go);
        cp16(base + sWl*2, gWl + go);
        cp_commit();
    }

    for (int ch = 0; ch < NCH; ch++) {
        if (ch < NCH - 1) cp_wait1(); else cp_wait0();   // chunk ch resident
        __syncthreads();
        if (ch + 2 < NCH) {        // issue chunk ch+2 into stage (ch+2)%3
            uint32_t base = smb + (uint32_t)(((ch + 2) % NSTG)*BUF_ELEM)*2;
            size_t go = (size_t)(ch + 2)*KC;
            cp16(base + sA0*2, gA0 + go*HW);
            cp16(base + sA1*2, gA1 + go*HW);
            cp16(base + sWh*2, gWh + go);
            cp16(base + sWl*2, gWl + go);
            cp_commit();
        }
        uint32_t bb0 = smb + (uint32_t)((ch % NSTG)*BUF_ELEM)*2;
#pragma unroll
        for (int g = 0; g < 2; g++) {                 // two k16 groups per chunk
            unsigned a[4];
            ldsm4t(a, bb0 + (uint32_t)((g*16 + arow)*SA_ROW + w*16 + apxl)*2);
            // pass 1: hi plane -> 8 independent accumulator chains
#pragma unroll
            for (int i = 0; i < 4; i++) {
                unsigned wh[4];
                ldsm4(wh, bb0 + (uint32_t)(SA_BUF + (i*16 + wrow)*SW_ROW + g*16 + wkl)*2);
                mma16816(acc[2*i],   a, wh[0], wh[1]);
                mma16816(acc[2*i+1], a, wh[2], wh[3]);
            }
            // pass 2: lo plane -> dependent mmas now >=8 issues downstream
#pragma unroll
            for (int i = 0; i < 4; i++) {
                unsigned wl[4];
                ldsm4(wl, bb0 + (uint32_t)(SA_BUF + SW_PLANE + (i*16 + wrow)*SW_ROW + g*16 + wkl)*2);
                mma16816(acc[2*i],   a, wl[0], wl[1]);
                mma16816(acc[2*i+1], a, wl[2], wl[3]);
            }
        }
        // stage (ch+2)%3 is written only after the next iteration's barrier.
    }

    float leak = *leak_ptr;
    leak = fminf(fmaxf(leak, 0.001f), 1000.0f);
    int mr = px0 + w*16 + (l >> 2);
#pragma unroll
    for (int nt = 0; nt < 8; nt++) {
        int o = nt*8 + (l & 3)*2;
        const float* po0 = embt  + (size_t)(b*NF + o)*HW;
        float*       pn0 = embt1 + (size_t)(b*NF + o)*HW;
        float bv0 = g_bias[b*NF + o];
        float bv1 = g_bias[b*NF + o + 1];
        pn0[mr]          = po0[mr]          + leak*(acc[nt][0] + bv0);
        pn0[mr + HW]     = po0[mr + HW]     + leak*(acc[nt][1] + bv1);
        pn0[mr + 8]      = po0[mr + 8]      + leak*(acc[nt][2] + bv0);
        pn0[mr + 8 + HW] = po0[mr + 8 + HW] + leak*(acc[nt][3] + bv1);
    }
}

// clipped RGB + raw RGB from the final state
__global__ void k_final(const float* __restrict__ emb_final, float* __restrict__ out) {
    int idx = blockIdx.x * 256 + threadIdx.x;     // < 196608
    int b = idx / (3*HW);
    int rem = idx - b*3*HW;
    int c = rem >> 12;
    int px = rem & 4095;
    float v = emb_final[((size_t)(b*NF + c))*HW + px];
    out[(size_t)OFF_RAW + idx] = v;
    out[idx] = fminf(fmaxf(v, -1.0f), 1.0f);
}

// ---------------------------------------------------------------------------
extern "C" void kernel_launch(void* const* d_in, const int* in_sizes, int n_in,
                              void* d_out, int out_size) {
    const float* lat  = (const float*)d_in[0];
    const float* Wk   = (const float*)d_in[1];
    const float* bk   = (const float*)d_in[2];
    const float* Wb   = (const float*)d_in[3];
    const float* bb   = (const float*)d_in[4];
    const float* leak = (const float*)d_in[5];
    float* out = (float*)d_out;

    cudaFuncSetAttribute(k_gemm, cudaFuncAttributeMaxDynamicSharedMemorySize, SMEM_BYTES);

    // ordering: harness issues 2 hidden launches first; ncu -s 5 -c 1 thus
    // profiles OUR launch #3 = the first k_gemm.
    k_init<<<EMB_SLICE/256, 256>>>(out + OFF_EMB);             // #0
    k_weights<<<49, 256>>>(lat, Wk, bk, Wb, bb);               // #1

    for (int t = 0; t < STEPS; t++) {
        const float* et  = out + (size_t)OFF_EMB + (size_t)t * EMB_SLICE;
        float*       et1 = out + (size_t)OFF_EMB + (size_t)(t + 1) * EMB_SLICE;
        k_stats<<<dim3(64, 16), 512>>>(et);                    // #2, #4, ...
        k_gemm<<<dim3(32, 16), 256, SMEM_BYTES>>>(et, et1, leak); // #3  <- ncu target
    }
    k_final<<<N_CLIP/256, 256>>>(out + OFF_EMB + (size_t)16*EMB_SLICE, out);
}